// round 13
// baseline (speedup 1.0000x reference)
#include <cuda_runtime.h>
#include <cuda_fp16.h>
#include <cstdint>

// Fixed problem shapes
#define BB    16
#define DC    16
#define ND    1024
#define CIN   64
#define COUT  128
#define NN    4096
#define KW    7
#define LT    128            // l-tile per CTA
#define NCH   8              // K chunks (8 channels each, 64 padded cols)
#define NTHR  1024           // 32 warps, one CTA per SM

// Scratch (device globals; no allocation allowed)
__device__ float g_z[BB*CIN*ND];
__device__ float g_scale[BB*CIN];
__device__ float g_shift[BB*CIN];
__device__ __align__(16) __half g_wH[NCH*COUT*64];   // [ch][o][col], col=cc*8+k

// ---------------- smem layout (bytes) ----------------
// M/W tiles: 128B rows with XOR swizzle (col16' = col16 ^ (row&7)) -> conflict-free
#define OFF_XS   0                    // xs fp32 [64][136] = 34816
#define OFF_XH   34816                // x  fp16 [64][136] = 17408
#define OFF_M    52224                // 8 chunks x 128 rows x 128B = 131072
#define OFF_W    183296               // 2 bufs x 128 rows x 128B = 32768
#define SMEM_TOTAL 216064

#define CP16(dst, src) asm volatile("cp.async.cg.shared.global [%0], [%1], 16;" :: "r"(dst), "l"(src) : "memory")
#define CPCOMMIT()     asm volatile("cp.async.commit_group;" ::: "memory")
#define CPWAIT0()      asm volatile("cp.async.wait_group 0;" ::: "memory")
#define CPWAIT1()      asm volatile("cp.async.wait_group 1;" ::: "memory")

__device__ __forceinline__ uint32_t smem_u32(const void* p) {
    uint32_t a;
    asm("{ .reg .u64 t; cvta.to.shared.u64 t, %1; cvt.u32.u64 %0, t; }" : "=r"(a) : "l"(p));
    return a;
}
__device__ __forceinline__ float rcpa(float x) {
    float r;
    asm("rcp.approx.f32 %0, %1;" : "=f"(r) : "f"(x));
    return r;
}
// pack(first, second) -> f16x2, first in bits[15:0]
__device__ __forceinline__ uint32_t packh(float a0, float a1) {
    uint32_t r;
    asm("cvt.rn.f16x2.f32 %0, %1, %2;" : "=r"(r) : "f"(a1), "f"(a0));
    return r;
}
#define LDSM4(r, a) \
    asm volatile("ldmatrix.sync.aligned.m8n8.x4.shared.b16 {%0,%1,%2,%3}, [%4];" \
        : "=r"((r)[0]), "=r"((r)[1]), "=r"((r)[2]), "=r"((r)[3]) : "r"(a))
#define MMAH(d, a, b0, b1) \
    asm volatile("mma.sync.aligned.m16n8k16.row.col.f32.f16.f16.f32 " \
        "{%0,%1,%2,%3},{%4,%5,%6,%7},{%8,%9},{%0,%1,%2,%3};" \
        : "+f"((d)[0]), "+f"((d)[1]), "+f"((d)[2]), "+f"((d)[3]) \
        : "r"((a)[0]), "r"((a)[1]), "r"((a)[2]), "r"((a)[3]), "r"(b0), "r"(b1))

// ---------------- kernel 1: fused z + stats + wsplit (unchanged from R11) ----------------
__global__ void k_prep(const float* __restrict__ deep, const float* __restrict__ conv_w,
                       const float* __restrict__ conv_b, const float* __restrict__ fc_w) {
    __shared__ float sz[ND];
    __shared__ float cw[DC];
    __shared__ float red1[8], red2[8];
    int bc  = blockIdx.x;
    int c   = bc & (CIN-1);
    int b   = bc >> 6;
    int tid = threadIdx.x;
    if (tid < 64) {
        int idx = bc*64 + tid;
        int ch  = idx >> 13;
        int o   = (idx >> 6) & 127;
        int col = idx & 63;
        int cc = col >> 3, k = col & 7;
        float v = (k < KW) ? fc_w[o*(CIN*KW) + (ch*8 + cc)*KW + k] : 0.f;
        g_wH[idx] = __float2half_rn(v);
    }
    if (tid < DC) cw[tid] = conv_w[c*DC + tid];
    __syncthreads();
    const float* dp = deep + (size_t)b*DC*ND;
    float* zrow = g_z + (size_t)bc*ND;
    for (int m = tid; m < ND; m += 256) {
        float acc = 0.f;
        #pragma unroll
        for (int d = 0; d < DC; ++d) acc += cw[d] * dp[(size_t)d*ND + m];
        sz[m] = acc;
        zrow[m] = acc;
    }
    __syncthreads();
    float bias = conv_b[c];
    float s1 = 0.f, s2 = 0.f;
    for (int n = tid; n < NN; n += 256) {
        float src = 0.25f*(float)n - 0.375f;
        src = fminf(fmaxf(src, 0.f), (float)(ND-1));
        int lo = (int)src;
        int hi = min(lo + 1, ND-1);
        float w = src - (float)lo;
        float v = sz[lo]*(1.f - w) + sz[hi]*w + bias;
        s1 += v; s2 += v*v;
    }
    #pragma unroll
    for (int off = 16; off; off >>= 1) {
        s1 += __shfl_down_sync(0xffffffffu, s1, off);
        s2 += __shfl_down_sync(0xffffffffu, s2, off);
    }
    if ((tid & 31) == 0) { red1[tid>>5] = s1; red2[tid>>5] = s2; }
    __syncthreads();
    if (tid == 0) {
        float t1 = 0.f, t2 = 0.f;
        #pragma unroll
        for (int i = 0; i < 8; ++i) { t1 += red1[i]; t2 += red2[i]; }
        float mean = t1 / (float)NN;
        float var  = (t2 - (float)NN*mean*mean) / (float)(NN-1);
        float sc   = 0.5f / (var + 1e-9f);
        g_scale[bc] = sc;
        g_shift[bc] = -sc * mean;
    }
}

// W chunk -> swizzled smem buffer: exactly 1 cp.async per thread (1024 = tile/16)
__device__ __forceinline__ void load_w(uint32_t dstbase, int ch, int tid) {
    const char* src = (const char*)(g_wH + (size_t)ch*COUT*64);
    int o = tid >> 3, seg = tid & 7;
    CP16(dstbase + (uint32_t)(o*128 + ((seg ^ (o & 7)) << 4)), src + (size_t)tid*16);
    CPCOMMIT();
}

// ---------------- kernel 2: one-shot build + pure HMMA GEMM ----------------
// grid (NN/LT=32, BB=16) = 512 CTAs, 1024 threads, 1 CTA/SM (32 warps/SM).
// Phase 1: stage xs(fp32)+x(fp16). Phase 2: build ALL 8 m-tiles. Phase 3: GEMM.
__global__ __launch_bounds__(NTHR, 1)
void k_tc(const float* __restrict__ x, const float* __restrict__ conv_b,
          float* __restrict__ out) {
    extern __shared__ __align__(16) char smem[];
    const uint32_t sb = smem_u32(smem);
    const int tid  = threadIdx.x;
    const int lane = tid & 31;
    const int wid  = tid >> 5;
    const int b    = blockIdx.y;
    const int l0   = blockIdx.x * LT;

    // prefetch first two W chunks
    load_w(sb + OFF_W,         0, tid);
    load_w(sb + OFF_W + 16384, 1, tid);

    // ---- phase 1: stage xs fp32 + x fp16, 64 ch x 134 positions (halo 3) ----
    float*  sxs = (float*) (smem + OFF_XS);
    __half* sxh = (__half*)(smem + OFF_XH);
    for (int t = tid; t < CIN*134; t += NTHR) {
        int c = t / 134, i = t - c*134;
        int p = l0 - 3 + i;
        if (p < 0)   p = -p;
        if (p >= NN) p = 2*NN - 2 - p;
        int bc = b*CIN + c;
        float src = 0.25f*(float)p - 0.375f;
        src = fminf(fmaxf(src, 0.f), (float)(ND-1));
        int lo = (int)src;
        int hi = min(lo + 1, ND-1);
        float w = src - (float)lo;
        const float* zrow = g_z + (size_t)bc*ND;
        float v = zrow[lo]*(1.f - w) + zrow[hi]*w + conv_b[c];
        sxs[c*136 + i] = g_scale[bc] * v + g_shift[bc];
        sxh[c*136 + i] = __float2half_rn(x[(size_t)bc*NN + p]);
    }
    __syncthreads();

    // ---- phase 2: build ALL m-tiles (8 tasks/thread, acc not yet live) ----
    {
        const int l  = tid & 127;
        const int cg = tid >> 7;                 // chunk this thread builds
        const unsigned swl = (unsigned)(l & 7);
        char* mrow = smem + OFF_M + cg*16384 + l*128;
        #pragma unroll 1
        for (int j = 0; j < 8; ++j) {
            int c = cg*8 + j;
            const float*  xsp = sxs + c*136 + l;
            const __half* xhp = sxh + c*136 + l;
            float ctr = xsp[3];
            #define RT(i) ({ float u_ = __expf(-2.0f*fabsf(xsp[i]-ctr)); float v_ = 1.0f + u_; u_ * rcpa(v_*v_); })
            float r0 = RT(0), r1 = RT(1), r2 = RT(2);
            float r4 = RT(4), r5 = RT(5), r6 = RT(6);
            #undef RT
            float den = ((r0 + r1) + (r2 + 0.25f)) + ((r4 + r5) + r6);
            float inv = rcpa(den);
            float m0v = __half2float(xhp[0]) * (r0 * inv);
            float m1v = __half2float(xhp[1]) * (r1 * inv);
            float m2v = __half2float(xhp[2]) * (r2 * inv);
            float m3v = __half2float(xhp[3]) * (0.25f * inv);
            float m4v = __half2float(xhp[4]) * (r4 * inv);
            float m5v = __half2float(xhp[5]) * (r5 * inv);
            float m6v = __half2float(xhp[6]) * (r6 * inv);
            uint32_t h0 = packh(m0v, m1v), h1 = packh(m2v, m3v);
            uint32_t h2 = packh(m4v, m5v), h3 = packh(m6v, 0.f);
            *(uint4*)(mrow + (((unsigned)j ^ swl) << 4)) = make_uint4(h0, h1, h2, h3);
        }
    }
    __syncthreads();                             // all M tiles ready

    // ---- phase 3: pure GEMM, warp tile 32o x 16l (4o x 8l warp grid) ----
    const int m0 = (wid & 3) * 32;
    const int n0 = (wid >> 2) * 16;
    const int rA = lane & 15, hA = (lane >> 4) & 1;
    const int rB = n0 + (lane & 7) + ((lane >> 4) & 1) * 8;
    const int hB = (lane >> 3) & 1;
    const uint32_t vA = (uint32_t)(hA ^ (rA & 7));     // col16 = vA ^ (2ks)
    const uint32_t vB = (uint32_t)(hB ^ (lane & 7));
    const uint32_t baseA0 = sb + OFF_W + (uint32_t)((m0 + rA) * 128);
    const uint32_t baseB0 = sb + OFF_M + (uint32_t)(rB * 128);

    float acc[2][2][4];
    #pragma unroll
    for (int i = 0; i < 2; ++i)
        #pragma unroll
        for (int n = 0; n < 2; ++n)
            #pragma unroll
            for (int r = 0; r < 4; ++r) acc[i][n][r] = 0.f;

    #pragma unroll 1
    for (int ch = 0; ch < NCH; ++ch) {
        if (ch >= NCH-2) { CPWAIT0(); } else { CPWAIT1(); }
        __syncthreads();                          // W(ch) visible to all
        const uint32_t bA = baseA0 + (uint32_t)((ch & 1) * 16384);
        const uint32_t bB = baseB0 + (uint32_t)(ch * 16384);
        #pragma unroll
        for (int ks = 0; ks < 4; ++ks) {
            uint32_t a0[4], a1[4], bm[4];
            const uint32_t cA = (vA ^ (uint32_t)(2*ks)) << 4;
            const uint32_t cB = (vB ^ (uint32_t)(2*ks)) << 4;
            LDSM4(a0, bA + cA);
            LDSM4(a1, bA + cA + 16*128);
            LDSM4(bm, bB + cB);
            MMAH(acc[0][0], a0, bm[0], bm[1]);
            MMAH(acc[0][1], a0, bm[2], bm[3]);
            MMAH(acc[1][0], a1, bm[0], bm[1]);
            MMAH(acc[1][1], a1, bm[2], bm[3]);
        }
        __syncthreads();                          // all readers done with W buf
        if (ch + 2 < NCH) load_w(sb + OFF_W + (uint32_t)((ch & 1) * 16384), ch + 2, tid);
    }

    // ---- epilogue: direct STG.64 ----
    const int g = lane >> 2, tq = lane & 3;
    float* outb = out + (size_t)b*COUT*NN + l0;
    #pragma unroll
    for (int i = 0; i < 2; ++i) {
        int o = m0 + i*16 + g;
        #pragma unroll
        for (int n = 0; n < 2; ++n) {
            int lp = n0 + n*8 + 2*tq;
            *(float2*)(outb + (size_t)o*NN + lp)     = make_float2(acc[i][n][0], acc[i][n][1]);
            *(float2*)(outb + (size_t)(o+8)*NN + lp) = make_float2(acc[i][n][2], acc[i][n][3]);
        }
    }
}

// ---------------- launch ----------------
extern "C" void kernel_launch(void* const* d_in, const int* in_sizes, int n_in,
                              void* d_out, int out_size) {
    const float* deep   = (const float*)d_in[0];
    const float* x      = (const float*)d_in[1];
    const float* conv_w = (const float*)d_in[2];
    const float* conv_b = (const float*)d_in[3];
    const float* fc_w   = (const float*)d_in[4];
    float* out = (float*)d_out;

    cudaFuncSetAttribute(k_tc, cudaFuncAttributeMaxDynamicSharedMemorySize, SMEM_TOTAL);

    k_prep<<<BB*CIN, 256>>>(deep, conv_w, conv_b, fc_w);
    k_tc  <<<dim3(NN/LT, BB), NTHR, SMEM_TOTAL>>>(x, conv_b, out);
}

// round 14
// speedup vs baseline: 1.2966x; 1.2966x over previous
#include <cuda_runtime.h>
#include <cuda_fp16.h>
#include <cstdint>

// Fixed problem shapes
#define BB    16
#define DC    16
#define ND    1024
#define CIN   64
#define COUT  128
#define NN    4096
#define KW    7
#define LT    64             // l-tile per CTA
#define NCH   8              // K chunks (8 channels each)
#define NTHR  256            // 8 warps, warp tile 32o x 32l

// Scratch (device globals; no allocation allowed)
__device__ float g_z[BB*CIN*ND];
__device__ float g_scale[BB*CIN];
__device__ float g_shift[BB*CIN];
__device__ __align__(16) __half g_wH[NCH*COUT*64];   // [ch][o][col], col=cc*8+k

// ---------------- smem layout (bytes) ----------------
// W/M tiles: 128B rows, XOR swizzle col16' = col16 ^ (row&7) -> conflict-free
#define OFF_XS   0                    // xs fp32 [64][70] = 17920
#define OFF_XH   17920                // x  fp16 [64][70] = 8960
#define OFF_ST   26880                // 2 stages x (W 16384 + M 8192)
#define T_W      0
#define T_M      16384
#define STAGE_BYTES 24576
#define SMEM_TOTAL (OFF_ST + 2*STAGE_BYTES)   // 76032 -> 3 CTAs/SM (228096 <= 228KB)

#define CP16(dst, src) asm volatile("cp.async.cg.shared.global [%0], [%1], 16;" :: "r"(dst), "l"(src) : "memory")
#define CPCOMMIT()     asm volatile("cp.async.commit_group;" ::: "memory")
#define CPWAIT0()      asm volatile("cp.async.wait_group 0;" ::: "memory")

__device__ __forceinline__ uint32_t smem_u32(const void* p) {
    uint32_t a;
    asm("{ .reg .u64 t; cvta.to.shared.u64 t, %1; cvt.u32.u64 %0, t; }" : "=r"(a) : "l"(p));
    return a;
}
__device__ __forceinline__ float rcpa(float x) {
    float r;
    asm("rcp.approx.f32 %0, %1;" : "=f"(r) : "f"(x));
    return r;
}
// pack(first, second) -> f16x2, first in bits[15:0]
__device__ __forceinline__ uint32_t packh(float a0, float a1) {
    uint32_t r;
    asm("cvt.rn.f16x2.f32 %0, %1, %2;" : "=r"(r) : "f"(a1), "f"(a0));
    return r;
}
#define LDSM4(r, a) \
    asm volatile("ldmatrix.sync.aligned.m8n8.x4.shared.b16 {%0,%1,%2,%3}, [%4];" \
        : "=r"((r)[0]), "=r"((r)[1]), "=r"((r)[2]), "=r"((r)[3]) : "r"(a))
#define MMAH(d, a, b0, b1) \
    asm volatile("mma.sync.aligned.m16n8k16.row.col.f32.f16.f16.f32 " \
        "{%0,%1,%2,%3},{%4,%5,%6,%7},{%8,%9},{%0,%1,%2,%3};" \
        : "+f"((d)[0]), "+f"((d)[1]), "+f"((d)[2]), "+f"((d)[3]) \
        : "r"((a)[0]), "r"((a)[1]), "r"((a)[2]), "r"((a)[3]), "r"(b0), "r"(b1))

// ---------------- kernel 1: fused z + stats + wsplit ----------------
__global__ void k_prep(const float* __restrict__ deep, const float* __restrict__ conv_w,
                       const float* __restrict__ conv_b, const float* __restrict__ fc_w) {
    __shared__ float sz[ND];
    __shared__ float cw[DC];
    __shared__ float red1[8], red2[8];
    int bc  = blockIdx.x;
    int c   = bc & (CIN-1);
    int b   = bc >> 6;
    int tid = threadIdx.x;
    if (tid < 64) {
        int idx = bc*64 + tid;
        int ch  = idx >> 13;
        int o   = (idx >> 6) & 127;
        int col = idx & 63;
        int cc = col >> 3, k = col & 7;
        float v = (k < KW) ? fc_w[o*(CIN*KW) + (ch*8 + cc)*KW + k] : 0.f;
        g_wH[idx] = __float2half_rn(v);
    }
    if (tid < DC) cw[tid] = conv_w[c*DC + tid];
    __syncthreads();
    const float* dp = deep + (size_t)b*DC*ND;
    float* zrow = g_z + (size_t)bc*ND;
    for (int m = tid; m < ND; m += 256) {
        float acc = 0.f;
        #pragma unroll
        for (int d = 0; d < DC; ++d) acc += cw[d] * dp[(size_t)d*ND + m];
        sz[m] = acc;
        zrow[m] = acc;
    }
    __syncthreads();
    float bias = conv_b[c];
    float s1 = 0.f, s2 = 0.f;
    for (int n = tid; n < NN; n += 256) {
        float src = 0.25f*(float)n - 0.375f;
        src = fminf(fmaxf(src, 0.f), (float)(ND-1));
        int lo = (int)src;
        int hi = min(lo + 1, ND-1);
        float w = src - (float)lo;
        float v = sz[lo]*(1.f - w) + sz[hi]*w + bias;
        s1 += v; s2 += v*v;
    }
    #pragma unroll
    for (int off = 16; off; off >>= 1) {
        s1 += __shfl_down_sync(0xffffffffu, s1, off);
        s2 += __shfl_down_sync(0xffffffffu, s2, off);
    }
    if ((tid & 31) == 0) { red1[tid>>5] = s1; red2[tid>>5] = s2; }
    __syncthreads();
    if (tid == 0) {
        float t1 = 0.f, t2 = 0.f;
        #pragma unroll
        for (int i = 0; i < 8; ++i) { t1 += red1[i]; t2 += red2[i]; }
        float mean = t1 / (float)NN;
        float var  = (t2 - (float)NN*mean*mean) / (float)(NN-1);
        float sc   = 0.5f / (var + 1e-9f);
        g_scale[bc] = sc;
        g_shift[bc] = -sc * mean;
    }
}

// W chunk -> swizzled smem (4 cp.async per thread)
__device__ __forceinline__ void load_w(uint32_t dstbase, int ch, int tid) {
    const char* src = (const char*)(g_wH + (size_t)ch*COUT*64);
    #pragma unroll
    for (int j = 0; j < 4; ++j) {
        int idx = tid + j*NTHR;          // 0..1023
        int o = idx >> 3, seg = idx & 7;
        CP16(dstbase + (uint32_t)(o*128 + ((seg ^ (o & 7)) << 4)), src + (size_t)idx*16);
    }
    CPCOMMIT();
}

// build one chunk's m tile: 2 tasks per thread (R11 math, fp16 x)
__device__ __forceinline__ void build_m(char* stage, int ch, int tid,
                                        const float* sxs, const __half* sxh) {
    #pragma unroll
    for (int t2 = 0; t2 < 2; ++t2) {
        int t  = tid + t2*NTHR;          // 0..511
        int l  = t & 63;
        int cc = t >> 6;                 // 0..7
        int c  = ch*8 + cc;
        const float*  xsp = sxs + c*70 + l;
        const __half* xhp = sxh + c*70 + l;
        float ctr = xsp[3];
        #define RT(i) ({ float u_ = __expf(-2.0f*fabsf(xsp[i]-ctr)); float v_ = 1.0f + u_; u_ * rcpa(v_*v_); })
        float r0 = RT(0), r1 = RT(1), r2 = RT(2);
        float r4 = RT(4), r5 = RT(5), r6 = RT(6);
        #undef RT
        float den = ((r0 + r1) + (r2 + 0.25f)) + ((r4 + r5) + r6);
        float inv = rcpa(den);
        float m0v = __half2float(xhp[0]) * (r0 * inv);
        float m1v = __half2float(xhp[1]) * (r1 * inv);
        float m2v = __half2float(xhp[2]) * (r2 * inv);
        float m3v = __half2float(xhp[3]) * (0.25f * inv);
        float m4v = __half2float(xhp[4]) * (r4 * inv);
        float m5v = __half2float(xhp[5]) * (r5 * inv);
        float m6v = __half2float(xhp[6]) * (r6 * inv);
        uint32_t h0 = packh(m0v, m1v), h1 = packh(m2v, m3v);
        uint32_t h2 = packh(m4v, m5v), h3 = packh(m6v, 0.f);
        *(uint4*)(stage + T_M + l*128 + (((unsigned)cc ^ (unsigned)(l & 7)) << 4)) =
            make_uint4(h0, h1, h2, h3);
    }
}

// ---------------- kernel 2: interleaved build + HMMA, 3 CTAs/SM ----------------
// grid (NN/LT=64, BB=16) = 1024 CTAs, 256 threads, warp tile 32o x 32l.
__global__ __launch_bounds__(NTHR, 3)
void k_tc(const float* __restrict__ x, const float* __restrict__ conv_b,
          float* __restrict__ out) {
    extern __shared__ __align__(16) char smem[];
    const uint32_t sb = smem_u32(smem);
    const int tid  = threadIdx.x;
    const int lane = tid & 31;
    const int wid  = tid >> 5;
    const int b    = blockIdx.y;
    const int l0   = blockIdx.x * LT;

    float*  sxs = (float*) (smem + OFF_XS);
    __half* sxh = (__half*)(smem + OFF_XH);

    load_w(sb + OFF_ST, 0, tid);        // W0 -> stage 0 (async)

    // ---- stage xs fp32 + x fp16, 64 ch x 70 positions (halo 3) ----
    for (int t = tid; t < CIN*70; t += NTHR) {
        int c = t / 70, i = t - c*70;
        int p = l0 - 3 + i;
        if (p < 0)   p = -p;
        if (p >= NN) p = 2*NN - 2 - p;
        int bc = b*CIN + c;
        float src = 0.25f*(float)p - 0.375f;
        src = fminf(fmaxf(src, 0.f), (float)(ND-1));
        int lo = (int)src;
        int hi = min(lo + 1, ND-1);
        float w = src - (float)lo;
        const float* zrow = g_z + (size_t)bc*ND;
        float v = zrow[lo]*(1.f - w) + zrow[hi]*w + conv_b[c];
        sxs[c*70 + i] = g_scale[bc] * v + g_shift[bc];
        sxh[c*70 + i] = __float2half_rn(x[(size_t)bc*NN + p]);
    }
    __syncthreads();

    build_m(smem + OFF_ST, 0, tid, sxs, sxh);
    CPWAIT0();
    __syncthreads();                    // stage 0 ready

    // warp tile 32o x 32l: 4 warps across o, 2 across l
    const int m0 = (wid & 3) * 32;
    const int n0 = (wid >> 2) * 32;
    const uint32_t vA = (uint32_t)(((lane >> 4) & 1) ^ (lane & 7));
    const uint32_t vB = (uint32_t)(((lane >> 3) & 1) ^ (lane & 7));
    const uint32_t rowA = (uint32_t)((m0 + (lane & 15)) * 128);
    const uint32_t rowB = (uint32_t)((n0 + (lane & 7) + 8*((lane >> 4) & 1)) * 128);

    float acc[2][4][4];
    #pragma unroll
    for (int i = 0; i < 2; ++i)
        #pragma unroll
        for (int n = 0; n < 4; ++n)
            #pragma unroll
            for (int r = 0; r < 4; ++r) acc[i][n][r] = 0.f;

    #pragma unroll 1
    for (int ch = 0; ch < NCH; ++ch) {
        const int s = ch & 1;
        const uint32_t stc = sb + (uint32_t)(OFF_ST + s*STAGE_BYTES);
        // produce next stage first (fills MMA stall slots)
        if (ch + 1 < NCH) {
            load_w(sb + (uint32_t)(OFF_ST + (s^1)*STAGE_BYTES), ch + 1, tid);
            build_m(smem + OFF_ST + (s^1)*STAGE_BYTES, ch + 1, tid, sxs, sxh);
        }
        // MMA on current stage
        const uint32_t bA = stc + T_W + rowA;
        const uint32_t bB = stc + T_M + rowB;
        #pragma unroll
        for (int ks = 0; ks < 4; ++ks) {
            uint32_t a0[4], a1[4], bm[4], bm2[4];
            const uint32_t cA = (vA ^ (uint32_t)(2*ks)) << 4;
            const uint32_t cB = (vB ^ (uint32_t)(2*ks)) << 4;
            LDSM4(a0, bA + cA);
            LDSM4(a1, bA + cA + 16*128);
            LDSM4(bm,  bB + cB);
            LDSM4(bm2, bB + cB + 16*128);
            MMAH(acc[0][0], a0, bm[0],  bm[1]);
            MMAH(acc[0][1], a0, bm[2],  bm[3]);
            MMAH(acc[0][2], a0, bm2[0], bm2[1]);
            MMAH(acc[0][3], a0, bm2[2], bm2[3]);
            MMAH(acc[1][0], a1, bm[0],  bm[1]);
            MMAH(acc[1][1], a1, bm[2],  bm[3]);
            MMAH(acc[1][2], a1, bm2[0], bm2[1]);
            MMAH(acc[1][3], a1, bm2[2], bm2[3]);
        }
        if (ch + 1 < NCH) CPWAIT0();
        __syncthreads();
    }

    // ---- epilogue: direct STG.64 ----
    const int g = lane >> 2, tq = lane & 3;
    float* outb = out + (size_t)b*COUT*NN + l0;
    #pragma unroll
    for (int i = 0; i < 2; ++i) {
        int o = m0 + i*16 + g;
        #pragma unroll
        for (int n = 0; n < 4; ++n) {
            int lp = n0 + n*8 + 2*tq;
            *(float2*)(outb + (size_t)o*NN + lp)     = make_float2(acc[i][n][0], acc[i][n][1]);
            *(float2*)(outb + (size_t)(o+8)*NN + lp) = make_float2(acc[i][n][2], acc[i][n][3]);
        }
    }
}

// ---------------- launch ----------------
extern "C" void kernel_launch(void* const* d_in, const int* in_sizes, int n_in,
                              void* d_out, int out_size) {
    const float* deep   = (const float*)d_in[0];
    const float* x      = (const float*)d_in[1];
    const float* conv_w = (const float*)d_in[2];
    const float* conv_b = (const float*)d_in[3];
    const float* fc_w   = (const float*)d_in[4];
    float* out = (float*)d_out;

    cudaFuncSetAttribute(k_tc, cudaFuncAttributeMaxDynamicSharedMemorySize, SMEM_TOTAL);

    k_prep<<<BB*CIN, 256>>>(deep, conv_w, conv_b, fc_w);
    k_tc  <<<dim3(NN/LT, BB), NTHR, SMEM_TOTAL>>>(x, conv_b, out);
}

// round 15
// speedup vs baseline: 1.3027x; 1.0047x over previous
#include <cuda_runtime.h>
#include <cuda_fp16.h>
#include <cstdint>

// Fixed problem shapes
#define BB    16
#define DC    16
#define ND    1024
#define CIN   64
#define COUT  128
#define NN    4096
#define KW    7
#define LT    64             // l-tile per CTA
#define NCH   8              // K chunks (8 channels each)
#define NTHR  256            // 8 warps, warp tile 32o x 32l

// Scratch (device globals; no allocation allowed)
__device__ float g_z[BB*CIN*ND];
__device__ float g_scale[BB*CIN];
__device__ float g_shift[BB*CIN];
__device__ __align__(16) __half g_wH[NCH*COUT*64];   // [ch][o][col], col=cc*8+k

// ---------------- smem layout (bytes) ----------------
// W/M tiles: 128B rows, XOR swizzle col16' = col16 ^ (row&7) -> conflict-free
#define OFF_E    0                    // E = exp(2*xs) fp32 [64][70] = 17920
#define OFF_XH   17920                // x  fp16 [64][70] = 8960
#define OFF_ST   26880                // 2 stages x (W 16384 + M 8192)
#define T_W      0
#define T_M      16384
#define STAGE_BYTES 24576
#define SMEM_TOTAL (OFF_ST + 2*STAGE_BYTES)   // 76032 -> 3 CTAs/SM

#define CP16(dst, src) asm volatile("cp.async.cg.shared.global [%0], [%1], 16;" :: "r"(dst), "l"(src) : "memory")
#define CPCOMMIT()     asm volatile("cp.async.commit_group;" ::: "memory")
#define CPWAIT0()      asm volatile("cp.async.wait_group 0;" ::: "memory")

__device__ __forceinline__ uint32_t smem_u32(const void* p) {
    uint32_t a;
    asm("{ .reg .u64 t; cvta.to.shared.u64 t, %1; cvt.u32.u64 %0, t; }" : "=r"(a) : "l"(p));
    return a;
}
__device__ __forceinline__ float rcpa(float x) {
    float r;
    asm("rcp.approx.f32 %0, %1;" : "=f"(r) : "f"(x));
    return r;
}
__device__ __forceinline__ float ex2a(float x) {
    float r;
    asm("ex2.approx.f32 %0, %1;" : "=f"(r) : "f"(x));
    return r;
}
// pack(first, second) -> f16x2, first in bits[15:0]
__device__ __forceinline__ uint32_t packh(float a0, float a1) {
    uint32_t r;
    asm("cvt.rn.f16x2.f32 %0, %1, %2;" : "=r"(r) : "f"(a1), "f"(a0));
    return r;
}
#define LDSM4(r, a) \
    asm volatile("ldmatrix.sync.aligned.m8n8.x4.shared.b16 {%0,%1,%2,%3}, [%4];" \
        : "=r"((r)[0]), "=r"((r)[1]), "=r"((r)[2]), "=r"((r)[3]) : "r"(a))
#define MMAH(d, a, b0, b1) \
    asm volatile("mma.sync.aligned.m16n8k16.row.col.f32.f16.f16.f32 " \
        "{%0,%1,%2,%3},{%4,%5,%6,%7},{%8,%9},{%0,%1,%2,%3};" \
        : "+f"((d)[0]), "+f"((d)[1]), "+f"((d)[2]), "+f"((d)[3]) \
        : "r"((a)[0]), "r"((a)[1]), "r"((a)[2]), "r"((a)[3]), "r"(b0), "r"(b1))

// ---------------- kernel 1: fused z + stats + wsplit ----------------
__global__ void k_prep(const float* __restrict__ deep, const float* __restrict__ conv_w,
                       const float* __restrict__ conv_b, const float* __restrict__ fc_w) {
    __shared__ float sz[ND];
    __shared__ float cw[DC];
    __shared__ float red1[8], red2[8];
    int bc  = blockIdx.x;
    int c   = bc & (CIN-1);
    int b   = bc >> 6;
    int tid = threadIdx.x;
    if (tid < 64) {
        int idx = bc*64 + tid;
        int ch  = idx >> 13;
        int o   = (idx >> 6) & 127;
        int col = idx & 63;
        int cc = col >> 3, k = col & 7;
        float v = (k < KW) ? fc_w[o*(CIN*KW) + (ch*8 + cc)*KW + k] : 0.f;
        g_wH[idx] = __float2half_rn(v);
    }
    if (tid < DC) cw[tid] = conv_w[c*DC + tid];
    __syncthreads();
    const float* dp = deep + (size_t)b*DC*ND;
    float* zrow = g_z + (size_t)bc*ND;
    for (int m = tid; m < ND; m += 256) {
        float acc = 0.f;
        #pragma unroll
        for (int d = 0; d < DC; ++d) acc += cw[d] * dp[(size_t)d*ND + m];
        sz[m] = acc;
        zrow[m] = acc;
    }
    __syncthreads();
    float bias = conv_b[c];
    float s1 = 0.f, s2 = 0.f;
    for (int n = tid; n < NN; n += 256) {
        float src = 0.25f*(float)n - 0.375f;
        src = fminf(fmaxf(src, 0.f), (float)(ND-1));
        int lo = (int)src;
        int hi = min(lo + 1, ND-1);
        float w = src - (float)lo;
        float v = sz[lo]*(1.f - w) + sz[hi]*w + bias;
        s1 += v; s2 += v*v;
    }
    #pragma unroll
    for (int off = 16; off; off >>= 1) {
        s1 += __shfl_down_sync(0xffffffffu, s1, off);
        s2 += __shfl_down_sync(0xffffffffu, s2, off);
    }
    if ((tid & 31) == 0) { red1[tid>>5] = s1; red2[tid>>5] = s2; }
    __syncthreads();
    if (tid == 0) {
        float t1 = 0.f, t2 = 0.f;
        #pragma unroll
        for (int i = 0; i < 8; ++i) { t1 += red1[i]; t2 += red2[i]; }
        float mean = t1 / (float)NN;
        float var  = (t2 - (float)NN*mean*mean) / (float)(NN-1);
        float sc   = 0.5f / (var + 1e-9f);
        g_scale[bc] = sc;
        g_shift[bc] = -sc * mean;
    }
}

// W chunk -> swizzled smem (4 cp.async per thread)
__device__ __forceinline__ void load_w(uint32_t dstbase, int ch, int tid) {
    const char* src = (const char*)(g_wH + (size_t)ch*COUT*64);
    #pragma unroll
    for (int j = 0; j < 4; ++j) {
        int idx = tid + j*NTHR;          // 0..1023
        int o = idx >> 3, seg = idx & 7;
        CP16(dstbase + (uint32_t)(o*128 + ((seg ^ (o & 7)) << 4)), src + (size_t)idx*16);
    }
    CPCOMMIT();
}

// build one chunk's m tile: 2 tasks per thread.
// r_k = E_k*E_3 / (E_k + E_3)^2  ==  u/(1+u)^2 with u = exp(-2|xs_k - xs_3|)
__device__ __forceinline__ void build_m(char* stage, int ch, int tid,
                                        const float* sE, const __half* sxh) {
    #pragma unroll
    for (int t2 = 0; t2 < 2; ++t2) {
        int t  = tid + t2*NTHR;          // 0..511
        int l  = t & 63;
        int cc = t >> 6;                 // 0..7
        int c  = ch*8 + cc;
        const float*  Ep  = sE  + c*70 + l;
        const __half* xhp = sxh + c*70 + l;
        float E3 = Ep[3];
        #define RT(i) ({ float e_ = Ep[i]; float su_ = e_ + E3; (e_ * E3) * rcpa(su_ * su_); })
        float r0 = RT(0), r1 = RT(1), r2 = RT(2);
        float r4 = RT(4), r5 = RT(5), r6 = RT(6);
        #undef RT
        float den = ((r0 + r1) + (r2 + 0.25f)) + ((r4 + r5) + r6);
        float inv = rcpa(den);
        float m0v = __half2float(xhp[0]) * (r0 * inv);
        float m1v = __half2float(xhp[1]) * (r1 * inv);
        float m2v = __half2float(xhp[2]) * (r2 * inv);
        float m3v = __half2float(xhp[3]) * (0.25f * inv);
        float m4v = __half2float(xhp[4]) * (r4 * inv);
        float m5v = __half2float(xhp[5]) * (r5 * inv);
        float m6v = __half2float(xhp[6]) * (r6 * inv);
        uint32_t h0 = packh(m0v, m1v), h1 = packh(m2v, m3v);
        uint32_t h2 = packh(m4v, m5v), h3 = packh(m6v, 0.f);
        *(uint4*)(stage + T_M + l*128 + (((unsigned)cc ^ (unsigned)(l & 7)) << 4)) =
            make_uint4(h0, h1, h2, h3);
    }
}

// ---------------- kernel 2: interleaved build + HMMA, 3 CTAs/SM ----------------
// grid (NN/LT=64, BB=16) = 1024 CTAs, 256 threads, warp tile 32o x 32l.
__global__ __launch_bounds__(NTHR, 3)
void k_tc(const float* __restrict__ x, const float* __restrict__ conv_b,
          float* __restrict__ out) {
    extern __shared__ __align__(16) char smem[];
    const uint32_t sb = smem_u32(smem);
    const int tid  = threadIdx.x;
    const int lane = tid & 31;
    const int wid  = tid >> 5;
    const int b    = blockIdx.y;
    const int l0   = blockIdx.x * LT;

    float*  sE  = (float*) (smem + OFF_E);
    __half* sxh = (__half*)(smem + OFF_XH);

    load_w(sb + OFF_ST, 0, tid);        // W0 -> stage 0 (async)

    // ---- stage E = exp(2*xs) fp32 + x fp16; thread -> (c = tid>>2, i stride 4) ----
    {
        const int c  = tid >> 2;        // 0..63
        const int i0 = tid & 3;
        const int bc = b*CIN + c;
        const float* zrow = g_z + (size_t)bc*ND;
        const float* xg   = x + (size_t)bc*NN;
        const float LOG2E2 = 2.8853900817779268f;   // 2*log2(e)
        const float sc2 = g_scale[bc] * LOG2E2;
        const float sh2 = g_shift[bc] * LOG2E2;
        const float cb  = conv_b[c];
        float*  Erow = sE  + c*70;
        __half* xrow = sxh + c*70;
        #pragma unroll 2
        for (int i = i0; i < 70; i += 4) {
            int p = l0 - 3 + i;
            if (p < 0)   p = -p;
            if (p >= NN) p = 2*NN - 2 - p;
            float src = 0.25f*(float)p - 0.375f;
            src = fminf(fmaxf(src, 0.f), (float)(ND-1));
            int lo = (int)src;
            int hi = min(lo + 1, ND-1);
            float w = src - (float)lo;
            float v = zrow[lo]*(1.f - w) + zrow[hi]*w + cb;   // y
            Erow[i] = ex2a(sc2 * v + sh2);                    // exp(2*xs)
            xrow[i] = __float2half_rn(xg[p]);
        }
    }
    __syncthreads();

    build_m(smem + OFF_ST, 0, tid, sE, sxh);
    CPWAIT0();
    __syncthreads();                    // stage 0 ready

    // warp tile 32o x 32l: 4 warps across o, 2 across l
    const int m0 = (wid & 3) * 32;
    const int n0 = (wid >> 2) * 32;
    const uint32_t vA = (uint32_t)(((lane >> 4) & 1) ^ (lane & 7));
    const uint32_t vB = (uint32_t)(((lane >> 3) & 1) ^ (lane & 7));
    const uint32_t rowA = (uint32_t)((m0 + (lane & 15)) * 128);
    const uint32_t rowB = (uint32_t)((n0 + (lane & 7) + 8*((lane >> 4) & 1)) * 128);

    float acc[2][4][4];
    #pragma unroll
    for (int i = 0; i < 2; ++i)
        #pragma unroll
        for (int n = 0; n < 4; ++n)
            #pragma unroll
            for (int r = 0; r < 4; ++r) acc[i][n][r] = 0.f;

    #pragma unroll 1
    for (int ch = 0; ch < NCH; ++ch) {
        const int s = ch & 1;
        const uint32_t stc = sb + (uint32_t)(OFF_ST + s*STAGE_BYTES);
        // produce next stage first (fills MMA stall slots)
        if (ch + 1 < NCH) {
            load_w(sb + (uint32_t)(OFF_ST + (s^1)*STAGE_BYTES), ch + 1, tid);
            build_m(smem + OFF_ST + (s^1)*STAGE_BYTES, ch + 1, tid, sE, sxh);
        }
        // MMA on current stage
        const uint32_t bA = stc + T_W + rowA;
        const uint32_t bB = stc + T_M + rowB;
        #pragma unroll
        for (int ks = 0; ks < 4; ++ks) {
            uint32_t a0[4], a1[4], bm[4], bm2[4];
            const uint32_t cA = (vA ^ (uint32_t)(2*ks)) << 4;
            const uint32_t cB = (vB ^ (uint32_t)(2*ks)) << 4;
            LDSM4(a0, bA + cA);
            LDSM4(a1, bA + cA + 16*128);
            LDSM4(bm,  bB + cB);
            LDSM4(bm2, bB + cB + 16*128);
            MMAH(acc[0][0], a0, bm[0],  bm[1]);
            MMAH(acc[0][1], a0, bm[2],  bm[3]);
            MMAH(acc[0][2], a0, bm2[0], bm2[1]);
            MMAH(acc[0][3], a0, bm2[2], bm2[3]);
            MMAH(acc[1][0], a1, bm[0],  bm[1]);
            MMAH(acc[1][1], a1, bm[2],  bm[3]);
            MMAH(acc[1][2], a1, bm2[0], bm2[1]);
            MMAH(acc[1][3], a1, bm2[2], bm2[3]);
        }
        if (ch + 1 < NCH) CPWAIT0();
        __syncthreads();
    }

    // ---- epilogue: direct STG.64 ----
    const int g = lane >> 2, tq = lane & 3;
    float* outb = out + (size_t)b*COUT*NN + l0;
    #pragma unroll
    for (int i = 0; i < 2; ++i) {
        int o = m0 + i*16 + g;
        #pragma unroll
        for (int n = 0; n < 4; ++n) {
            int lp = n0 + n*8 + 2*tq;
            *(float2*)(outb + (size_t)o*NN + lp)     = make_float2(acc[i][n][0], acc[i][n][1]);
            *(float2*)(outb + (size_t)(o+8)*NN + lp) = make_float2(acc[i][n][2], acc[i][n][3]);
        }
    }
}

// ---------------- launch ----------------
extern "C" void kernel_launch(void* const* d_in, const int* in_sizes, int n_in,
                              void* d_out, int out_size) {
    const float* deep   = (const float*)d_in[0];
    const float* x      = (const float*)d_in[1];
    const float* conv_w = (const float*)d_in[2];
    const float* conv_b = (const float*)d_in[3];
    const float* fc_w   = (const float*)d_in[4];
    float* out = (float*)d_out;

    cudaFuncSetAttribute(k_tc, cudaFuncAttributeMaxDynamicSharedMemorySize, SMEM_TOTAL);

    k_prep<<<BB*CIN, 256>>>(deep, conv_w, conv_b, fc_w);
    k_tc  <<<dim3(NN/LT, BB), NTHR, SMEM_TOTAL>>>(x, conv_b, out);
}